// round 12
// baseline (speedup 1.0000x reference)
#include <cuda_runtime.h>
#include <math.h>
#include <stdint.h>

#define B_TOTAL 16384

// ---------------- scratch (device globals; no allocation allowed) ----------
__device__ float g_h1[B_TOTAL * 6 * 14 * 14];   // after conv1+relu+pool
__device__ float g_h2[B_TOTAL * 400];           // after conv2+relu+pool (flat)
__device__ float g_h3[B_TOTAL * 120];           // after fc1+relu
__device__ float g_h4[B_TOTAL * 84];            // after fc2+relu

// pre-converted tf32 expert weights, PAIRWISE layout for float2 B-frag loads:
// W1p: [cc][n=0..63][ks=0..10][tig=0..3][2]  value pair = w1[e][8ks+tig(+4)][c*64+n]
// W2p: [cc][d=0..95][hb=0..7][tig=0..3][2]   value pair = w2[e][c*64+8hb+tig(+4)][d]
#define W1CH 5632
#define W2CH 6912
__device__ float g_w1t[64 * W1CH];
__device__ float g_w2t[64 * W2CH];

// ---------------------------------------------------------------------------
// helpers
// ---------------------------------------------------------------------------
__device__ __forceinline__ float to_tf32(float f) {
    uint32_t u;
    asm("cvt.rna.tf32.f32 %0, %1;" : "=r"(u) : "f"(f));
    return __uint_as_float(u);
}

__device__ __forceinline__ void mma_tf32(float c[4],
                                         uint32_t a0, uint32_t a1, uint32_t a2, uint32_t a3,
                                         uint32_t b0, uint32_t b1) {
    asm volatile(
        "mma.sync.aligned.m16n8k8.row.col.f32.tf32.tf32.f32 "
        "{%0,%1,%2,%3}, {%4,%5,%6,%7}, {%8,%9}, {%0,%1,%2,%3};\n"
        : "+f"(c[0]), "+f"(c[1]), "+f"(c[2]), "+f"(c[3])
        : "r"(a0), "r"(a1), "r"(a2), "r"(a3), "r"(b0), "r"(b1));
}

#define CP16(dst, src) \
    asm volatile("cp.async.cg.shared.global [%0], [%1], 16;\n" \
                 :: "r"(dst), "l"(src))

// ---------------------------------------------------------------------------
// weight pre-pass kernels (pairwise repack + tf32 convert)
// ---------------------------------------------------------------------------
__global__ __launch_bounds__(256) void prep_w1(const float* __restrict__ w1)
{
    int idx = blockIdx.x * 256 + threadIdx.x;
    if (idx >= 64 * W1CH) return;
    int cc = idx / W1CH;
    int r  = idx % W1CH;
    int n  = r / 88;
    int q  = r % 88;
    int ks = q >> 3;
    int tig = (q & 7) >> 1;
    int h  = q & 1;
    int k  = ks * 8 + tig + h * 4;
    int e  = cc >> 5, c = cc & 31;
    float v = 0.f;
    if (k < 84) v = to_tf32(w1[((size_t)e * 84 + k) * 2048 + c * 64 + n]);
    g_w1t[idx] = v;
}

__global__ __launch_bounds__(256) void prep_w2(const float* __restrict__ w2)
{
    int idx = blockIdx.x * 256 + threadIdx.x;
    if (idx >= 64 * W2CH) return;
    int cc = idx / W2CH;
    int r  = idx % W2CH;
    int d  = r / 72;
    int q  = r % 72;
    float v = 0.f;
    if (q < 64) {
        int hb  = q >> 3;
        int tig = (q & 7) >> 1;
        int h   = q & 1;
        int kk  = hb * 8 + tig + h * 4;
        int e   = cc >> 5, c = cc & 31;
        if (d < 84) v = to_tf32(w2[((size_t)e * 2048 + c * 64 + kk) * 84 + d]);
    }
    g_w2t[idx] = v;
}

// ---------------------------------------------------------------------------
// conv1: x[B,3,32,32] -> relu(maxpool2(conv 5x5, 6ch)) -> [B,6,14,14]
// 3 images/block, 608 threads (19 warps, 588 active = 96.7%).  (R11 winner)
// ---------------------------------------------------------------------------
__global__ __launch_bounds__(608, 1) void conv1_kernel(
    const float* __restrict__ x, const float* __restrict__ w,
    const float* __restrict__ b, float* __restrict__ out, int B)
{
    __shared__ float s_img[3 * 3072];
    __shared__ float s_w[450];
    __shared__ float s_b[8];

    int img0 = blockIdx.x * 3;
    int nimg = B - img0; if (nimg > 3) nimg = 3;
    int tid = threadIdx.x;

    for (int i = tid; i < 450; i += 608) s_w[i] = w[i];
    if (tid < 6) s_b[tid] = b[tid];
    {
        const float* src = x + (size_t)img0 * 3072;
        int total = nimg * 3072;
        for (int i = tid; i < total; i += 608) s_img[i] = src[i];
    }
    __syncthreads();

    if (tid >= nimg * 196) return;
    int img = tid / 196;
    int r   = tid % 196;
    int py = r / 14;
    int px = r % 14;

    float acc[24];
#pragma unroll
    for (int i = 0; i < 24; i++) acc[i] = 0.f;

#pragma unroll
    for (int ic = 0; ic < 3; ic++) {
        float p[36];
        const float* ib = s_img + img * 3072 + ic * 1024 + (2 * py) * 32 + 2 * px;
#pragma unroll
        for (int ry = 0; ry < 6; ry++)
#pragma unroll
            for (int rx = 0; rx < 6; rx++)
                p[ry * 6 + rx] = ib[ry * 32 + rx];
#pragma unroll
        for (int oc = 0; oc < 6; oc++) {
            float wr[25];
#pragma unroll
            for (int i = 0; i < 25; i++) wr[i] = s_w[oc * 75 + ic * 25 + i];
#pragma unroll
            for (int ky = 0; ky < 5; ky++)
#pragma unroll
                for (int kx = 0; kx < 5; kx++) {
                    float wv = wr[ky * 5 + kx];
                    acc[oc * 4 + 0] += p[ ky      * 6 + kx    ] * wv;
                    acc[oc * 4 + 1] += p[ ky      * 6 + kx + 1] * wv;
                    acc[oc * 4 + 2] += p[(ky + 1) * 6 + kx    ] * wv;
                    acc[oc * 4 + 3] += p[(ky + 1) * 6 + kx + 1] * wv;
                }
        }
    }

    float* ob = out + (size_t)(img0 + img) * 1176 + py * 14 + px;
#pragma unroll
    for (int oc = 0; oc < 6; oc++) {
        float m = fmaxf(fmaxf(acc[oc * 4 + 0], acc[oc * 4 + 1]),
                        fmaxf(acc[oc * 4 + 2], acc[oc * 4 + 3]));
        ob[oc * 196] = fmaxf(m + s_b[oc], 0.f);
    }
}

// ---------------------------------------------------------------------------
// conv2: h1[B,6,14,14] -> relu(maxpool2(conv 5x5, 16ch)) -> [B,16,5,5] flat 400
// ---------------------------------------------------------------------------
__global__ __launch_bounds__(256) void conv2_kernel(
    const float* __restrict__ in, const float* __restrict__ w,
    const float* __restrict__ b, float* __restrict__ out, int B)
{
    __shared__ float s_in[3 * 1176];
    __shared__ float s_w[2400];
    __shared__ float s_b[16];

    int img0 = blockIdx.x * 3;
    int nimg = B - img0; if (nimg > 3) nimg = 3;

    for (int i = threadIdx.x; i < 2400; i += 256) s_w[i] = w[i];
    if (threadIdx.x < 16) s_b[threadIdx.x] = b[threadIdx.x];
    {
        const float* src = in + (size_t)img0 * 1176;
        int total = nimg * 1176;
        for (int i = threadIdx.x; i < total; i += 256) s_in[i] = src[i];
    }
    __syncthreads();

    int t = threadIdx.x;
    if (t >= nimg * 80) return;
    int img = t / 80;
    int r   = t % 80;
    int oc  = r / 5;
    int py  = r % 5;

    float acc[20];
#pragma unroll
    for (int i = 0; i < 20; i++) acc[i] = 0.f;

#pragma unroll
    for (int ic = 0; ic < 6; ic++) {
        float wreg[25];
#pragma unroll
        for (int i = 0; i < 25; i++) wreg[i] = s_w[oc * 150 + ic * 25 + i];
        const float* ib = s_in + img * 1176 + ic * 196 + (2 * py) * 14;
#pragma unroll
        for (int px = 0; px < 5; px++) {
            float p[36];
#pragma unroll
            for (int ry = 0; ry < 6; ry++)
#pragma unroll
                for (int rx = 0; rx < 6; rx++)
                    p[ry * 6 + rx] = ib[ry * 14 + 2 * px + rx];
#pragma unroll
            for (int ky = 0; ky < 5; ky++)
#pragma unroll
                for (int kx = 0; kx < 5; kx++) {
                    float wv = wreg[ky * 5 + kx];
                    acc[px * 4 + 0] += p[ ky      * 6 + kx    ] * wv;
                    acc[px * 4 + 1] += p[ ky      * 6 + kx + 1] * wv;
                    acc[px * 4 + 2] += p[(ky + 1) * 6 + kx    ] * wv;
                    acc[px * 4 + 3] += p[(ky + 1) * 6 + kx + 1] * wv;
                }
        }
    }
    float bias = s_b[oc];
    float* obase = out + (size_t)(img0 + img) * 400 + oc * 25 + py * 5;
#pragma unroll
    for (int px = 0; px < 5; px++) {
        float m = fmaxf(fmaxf(acc[px * 4 + 0], acc[px * 4 + 1]),
                        fmaxf(acc[px * 4 + 2], acc[px * 4 + 3]));
        obase[px] = fmaxf(m + bias, 0.f);
    }
}

// ---------------------------------------------------------------------------
// Generic tiled GEMM: C[M,N] = act(A[M,K] @ W[K,N] + bias), 64x64x16 tiles.
// ---------------------------------------------------------------------------
__global__ __launch_bounds__(256) void gemm_bias_relu(
    const float* __restrict__ A, const float* __restrict__ W,
    const float* __restrict__ bias, float* __restrict__ C,
    int M, int N, int K, int doRelu)
{
    __shared__ float As[16][65];
    __shared__ float Ws[16][64];

    int n0 = blockIdx.x * 64;
    int m0 = blockIdx.y * 64;
    int tx = threadIdx.x & 15;
    int ty = threadIdx.x >> 4;

    float acc[4][4];
#pragma unroll
    for (int i = 0; i < 4; i++)
#pragma unroll
        for (int j = 0; j < 4; j++) acc[i][j] = 0.f;

    for (int k0 = 0; k0 < K; k0 += 16) {
#pragma unroll
        for (int q = 0; q < 4; q++) {
            int idx = threadIdx.x + q * 256;
            int m = idx >> 4, kk = idx & 15;
            int gk = k0 + kk;
            As[kk][m] = (gk < K) ? A[(size_t)(m0 + m) * K + gk] : 0.f;
        }
#pragma unroll
        for (int q = 0; q < 4; q++) {
            int idx = threadIdx.x + q * 256;
            int kk = idx >> 6, n = idx & 63;
            int gk = k0 + kk, gn = n0 + n;
            Ws[kk][n] = (gk < K && gn < N) ? W[(size_t)gk * N + gn] : 0.f;
        }
        __syncthreads();
#pragma unroll
        for (int kk = 0; kk < 16; kk++) {
            float a[4], bb[4];
#pragma unroll
            for (int i = 0; i < 4; i++) a[i] = As[kk][ty + 16 * i];
#pragma unroll
            for (int j = 0; j < 4; j++) bb[j] = Ws[kk][tx + 16 * j];
#pragma unroll
            for (int i = 0; i < 4; i++)
#pragma unroll
                for (int j = 0; j < 4; j++) acc[i][j] += a[i] * bb[j];
        }
        __syncthreads();
    }

#pragma unroll
    for (int i = 0; i < 4; i++) {
        int m = m0 + ty + 16 * i;
#pragma unroll
        for (int j = 0; j < 4; j++) {
            int n = n0 + tx + 16 * j;
            if (n < N && m < M) {
                float v = acc[i][j] + bias[n];
                if (doRelu) v = fmaxf(v, 0.f);
                C[(size_t)m * N + n] = v;
            }
        }
    }
}

// ---------------------------------------------------------------------------
// Fused MoE + fc3, tf32 mma. 128 tokens/block, 512 threads (16 warps).
// Warp PAIR (w, w+8) owns 16 token rows; low warp handles hidden cols 0..31
// of each chunk, high warp cols 32..63. H stays in registers per warp
// (its GEMM2 k-range == its own H cols). Partial accY reduced via Y_s at end.
// Pairwise weight layout -> float2 (LDS.64) B-fragment loads.
// ---------------------------------------------------------------------------
#define XS_STRIDE 92
// smem float offsets
#define OFF_X    0                                  // 128*92 = 11776
#define OFF_W1   (128 * XS_STRIDE)                  // 11776  (2 bufs x 5632)
#define OFF_W2   (OFF_W1 + 2 * W1CH)                // 23040  (2 bufs x 6912)
#define OFF_B1   (OFF_W2 + 2 * W2CH)                // 36864  (2 x 64)
#define OFF_GW   (OFF_B1 + 128)                     // 36992
#define OFF_C    (OFF_GW + 168)                     // 37160
#define OFF_B2   (OFF_C + 256)                      // 37416
#define OFF_W3   (OFF_B2 + 168)                     // 37584
#define OFF_B3   (OFF_W3 + 840)                     // 38424
#define MOE_SMEM_FLOATS (OFF_B3 + 16)               // 38440 (153.8 KB)

__global__ __launch_bounds__(512, 1) void moe_fc3_kernel(
    const float* __restrict__ x,      // [B,84]
    const float* __restrict__ gate_w, // [84,2]
    const float* __restrict__ b1g,    // [2,2048]
    const float* __restrict__ b2,     // [2,84]
    const float* __restrict__ w3,     // [84,10]
    const float* __restrict__ b3,     // [10]
    float* __restrict__ out)          // [B,10]
{
    extern __shared__ float sm[];
    float* X_s  = sm + OFF_X;
    float* W1_s = sm + OFF_W1;
    float* W2_s = sm + OFF_W2;
    float* sb1  = sm + OFF_B1;
    float* sgw  = sm + OFF_GW;
    float* c_s  = sm + OFF_C;
    float* sb2  = sm + OFF_B2;
    float* sw3  = sm + OFF_W3;
    float* sb3  = sm + OFF_B3;

    const int tid = threadIdx.x;
    const int t0  = blockIdx.x * 128;

    const uint32_t smbase = (uint32_t)__cvta_generic_to_shared(sm);
    const uint32_t w1_sm  = smbase + OFF_W1 * 4;
    const uint32_t w2_sm  = smbase + OFF_W2 * 4;
    const uint32_t b1_sm  = smbase + OFF_B1 * 4;

    // ---- prologue: async-load chunk 0 weights into buffer 0 ----
    {
        const float4* s1 = (const float4*)(g_w1t);
        for (int i = tid; i < W1CH / 4; i += 512) CP16(w1_sm + i * 16, s1 + i);
        const float4* s2 = (const float4*)(g_w2t);
        for (int i = tid; i < W2CH / 4; i += 512) CP16(w2_sm + i * 16, s2 + i);
        if (tid < 16) CP16(b1_sm + tid * 16, (const float4*)b1g + tid);
    }
    asm volatile("cp.async.commit_group;\n" ::: "memory");

    // ---- sync loads: X + constants ----
    for (int i = tid; i < 128 * 84; i += 512) {
        int t = i / 84, k = i % 84;
        X_s[t * XS_STRIDE + k] = x[(size_t)(t0 + t) * 84 + k];
    }
    for (int i = tid; i < 128 * 8; i += 512) {
        int t = i / 8, k = 84 + (i % 8);
        X_s[t * XS_STRIDE + k] = 0.f;
    }
    for (int i = tid; i < 168; i += 512) sgw[i] = gate_w[i];
    for (int i = tid; i < 168; i += 512) sb2[i] = b2[i];
    for (int i = tid; i < 840; i += 512) sw3[i] = w3[i];
    if (tid < 10) sb3[tid] = b3[tid];
    __syncthreads();

    // ---- gate: softmax over 2 logits (top-2 of 2 + renorm == softmax) ----
    if (tid < 128) {
        float l0 = 0.f, l1 = 0.f;
        const float* xr = X_s + tid * XS_STRIDE;
#pragma unroll 4
        for (int k = 0; k < 84; k++) {
            l0 += xr[k] * sgw[k * 2 + 0];
            l1 += xr[k] * sgw[k * 2 + 1];
        }
        float m = fmaxf(l0, l1);
        float e0 = expf(l0 - m), e1 = expf(l1 - m);
        float inv = 1.f / (e0 + e1);
        c_s[tid * 2 + 0] = e0 * inv;
        c_s[tid * 2 + 1] = e1 * inv;
    }
    __syncthreads();

    // ---- convert X to tf32 in place ----
    for (int i = tid; i < 128 * XS_STRIDE; i += 512) X_s[i] = to_tf32(X_s[i]);
    __syncthreads();

    const int lane = tid & 31, wid = tid >> 5;
    const int gid = lane >> 2, tig = lane & 3;
    const int half = wid >> 3;                 // 0: hidden cols 0..31, 1: 32..63
    const int wq   = wid & 7;
    const int wm   = wq * 16;                  // row group owned by the pair
    const int noff = half * 32;                // this warp's hidden-col offset
    const int L0  = (lane & 0x1C) + (tig >> 1);  // shuffle src for cols t
    const int L2  = L0 + 2;                      // shuffle src for cols t+4
    const bool odd = (tig & 1);

    // per-row gates (loop-invariant)
    const float gA0 = c_s[(wm + gid    ) * 2 + 0];
    const float gA1 = c_s[(wm + gid    ) * 2 + 1];
    const float gB0 = c_s[(wm + gid + 8) * 2 + 0];
    const float gB1 = c_s[(wm + gid + 8) * 2 + 1];

    float accY[12][4];
#pragma unroll
    for (int nb = 0; nb < 12; nb++)
#pragma unroll
        for (int r = 0; r < 4; r++) accY[nb][r] = 0.f;

    for (int cc = 0; cc < 64; cc++) {
        const int buf = cc & 1;
        const int e   = cc >> 5;

        asm volatile("cp.async.wait_group 0;\n" ::: "memory");
        __syncthreads();   // weights for chunk cc resident; prior chunk done

        // prefetch chunk cc+1 into the other buffer
        if (cc + 1 < 64) {
            const int nb2 = buf ^ 1;
            const float4* s1 = (const float4*)(g_w1t + (size_t)(cc + 1) * W1CH);
            uint32_t d1 = w1_sm + nb2 * (W1CH * 4);
            for (int i = tid; i < W1CH / 4; i += 512) CP16(d1 + i * 16, s1 + i);
            const float4* s2 = (const float4*)(g_w2t + (size_t)(cc + 1) * W2CH);
            uint32_t d2 = w2_sm + nb2 * (W2CH * 4);
            for (int i = tid; i < W2CH / 4; i += 512) CP16(d2 + i * 16, s2 + i);
            if (tid < 16)
                CP16(b1_sm + nb2 * 256 + tid * 16,
                     (const float4*)(b1g + (size_t)(cc + 1) * 64) + tid);
        }
        asm volatile("cp.async.commit_group;\n" ::: "memory");

        const float2* W1b = (const float2*)(W1_s + buf * W1CH);
        const float2* W2b = (const float2*)(W2_s + buf * W2CH);
        const float* b1b = sb1 + buf * 64;

        const float gl = e ? gA1 : gA0;   // gate for rows wm+gid
        const float gh = e ? gB1 : gB0;   // gate for rows wm+gid+8

        // ---- GEMM1: accA = X(16x88) @ W1(88x32), this warp's half ----
        float accA[4][4];
#pragma unroll
        for (int nb = 0; nb < 4; nb++)
#pragma unroll
            for (int r = 0; r < 4; r++) accA[nb][r] = 0.f;

#pragma unroll
        for (int ks = 0; ks < 11; ks++) {
            int k = ks * 8 + tig;
            uint32_t a0 = __float_as_uint(X_s[(wm + gid    ) * XS_STRIDE + k    ]);
            uint32_t a1 = __float_as_uint(X_s[(wm + gid + 8) * XS_STRIDE + k    ]);
            uint32_t a2 = __float_as_uint(X_s[(wm + gid    ) * XS_STRIDE + k + 4]);
            uint32_t a3 = __float_as_uint(X_s[(wm + gid + 8) * XS_STRIDE + k + 4]);
#pragma unroll
            for (int nb = 0; nb < 4; nb++) {
                int n = noff + nb * 8 + gid;
                float2 bp = W1b[n * 44 + ks * 4 + tig];
                mma_tf32(accA[nb], a0, a1, a2, a3,
                         __float_as_uint(bp.x), __float_as_uint(bp.y));
            }
        }

        // ---- epilogue (regs) + GEMM2 partial over this warp's k-half ----
#pragma unroll
        for (int hbl = 0; hbl < 4; hbl++) {
            int hb = half * 4 + hbl;          // global 8-col block in chunk
            int n0 = hb * 8 + 2 * tig;
            float ba = b1b[n0], bbv = b1b[n0 + 1];
            float h0 = to_tf32(fmaxf(accA[hbl][0] + ba , 0.f) * gl);
            float h1 = to_tf32(fmaxf(accA[hbl][1] + bbv, 0.f) * gl);
            float h2 = to_tf32(fmaxf(accA[hbl][2] + ba , 0.f) * gh);
            float h3 = to_tf32(fmaxf(accA[hbl][3] + bbv, 0.f) * gh);

            // shuffle C-frag -> A-frag
            float u0 = __shfl_sync(0xFFFFFFFFu, h0, L0);
            float u1 = __shfl_sync(0xFFFFFFFFu, h1, L0);
            float u2 = __shfl_sync(0xFFFFFFFFu, h2, L0);
            float u3 = __shfl_sync(0xFFFFFFFFu, h3, L0);
            float v0 = __shfl_sync(0xFFFFFFFFu, h0, L2);
            float v1 = __shfl_sync(0xFFFFFFFFu, h1, L2);
            float v2 = __shfl_sync(0xFFFFFFFFu, h2, L2);
            float v3 = __shfl_sync(0xFFFFFFFFu, h3, L2);
            uint32_t a0 = __float_as_uint(odd ? u1 : u0);
            uint32_t a1 = __float_as_uint(odd ? u3 : u2);
            uint32_t a2 = __float_as_uint(odd ? v1 : v0);
            uint32_t a3 = __float_as_uint(odd ? v3 : v2);

#pragma unroll
            for (int nb = 0; nb < 12; nb++) {
                int n = nb * 8 + gid;
                float2 bp = W2b[n * 36 + hb * 4 + tig];
                mma_tf32(accY[nb], a0, a1, a2, a3,
                         __float_as_uint(bp.x), __float_as_uint(bp.y));
            }
        }
    }

    // ---- reduce warp-pair partials into Y_s, then fc3 ----
    __syncthreads();   // all warps done with final chunk's weights
    float* Y_s = W1_s;   // 2*5632 = 11264 >= 128*84 = 10752

    if (half == 0) {   // low warps: write partial + combined b2
#pragma unroll
        for (int nb = 0; nb < 12; nb++) {
            int d = nb * 8 + 2 * tig;
            if (d < 84) {
                float bc = gA0 * sb2[d] + gA1 * sb2[84 + d];
                float bh = gB0 * sb2[d] + gB1 * sb2[84 + d];
                Y_s[(wm + gid    ) * 84 + d] = accY[nb][0] + bc;
                Y_s[(wm + gid + 8) * 84 + d] = accY[nb][2] + bh;
            }
            if (d + 1 < 84) {
                float bc = gA0 * sb2[d + 1] + gA1 * sb2[84 + d + 1];
                float bh = gB0 * sb2[d + 1] + gB1 * sb2[84 + d + 1];
                Y_s[(wm + gid    ) * 84 + d + 1] = accY[nb][1] + bc;
                Y_s[(wm + gid + 8) * 84 + d + 1] = accY[nb][3] + bh;
            }
        }
    }
    __syncthreads();
    if (half == 1) {   // high warps: add their partial
#pragma unroll
        for (int nb = 0; nb < 12; nb++) {
            int d = nb * 8 + 2 * tig;
            if (d < 84) {
                Y_s[(wm + gid    ) * 84 + d] += accY[nb][0];
                Y_s[(wm + gid + 8) * 84 + d] += accY[nb][2];
            }
            if (d + 1 < 84) {
                Y_s[(wm + gid    ) * 84 + d + 1] += accY[nb][1];
                Y_s[(wm + gid + 8) * 84 + d + 1] += accY[nb][3];
            }
        }
    }
    __syncthreads();

    // fc3: [128,84] @ [84,10] + b3
    for (int o = tid; o < 1280; o += 512) {
        int t = o / 10, cc = o % 10;
        float s = sb3[cc];
        const float* yr = Y_s + t * 84;
#pragma unroll 4
        for (int d = 0; d < 84; d++) s += yr[d] * sw3[d * 10 + cc];
        out[(size_t)(t0 + t) * 10 + cc] = s;
    }
}

// ---------------------------------------------------------------------------
extern "C" void kernel_launch(void* const* d_in, const int* in_sizes, int n_in,
                              void* d_out, int out_size)
{
    const float* x       = (const float*)d_in[0];
    const float* conv1_w = (const float*)d_in[1];
    const float* conv1_b = (const float*)d_in[2];
    const float* conv2_w = (const float*)d_in[3];
    const float* conv2_b = (const float*)d_in[4];
    const float* fc1_w   = (const float*)d_in[5];
    const float* fc1_b   = (const float*)d_in[6];
    const float* fc2_w   = (const float*)d_in[7];
    const float* fc2_b   = (const float*)d_in[8];
    const float* gate_w  = (const float*)d_in[9];
    const float* exp_w1  = (const float*)d_in[10];
    const float* exp_b1  = (const float*)d_in[11];
    const float* exp_w2  = (const float*)d_in[12];
    const float* exp_b2  = (const float*)d_in[13];
    const float* fc3_w   = (const float*)d_in[14];
    const float* fc3_b   = (const float*)d_in[15];
    float* out = (float*)d_out;

    const int B = B_TOTAL;

    float *h1, *h2, *h3, *h4;
    cudaGetSymbolAddress((void**)&h1, g_h1);
    cudaGetSymbolAddress((void**)&h2, g_h2);
    cudaGetSymbolAddress((void**)&h3, g_h3);
    cudaGetSymbolAddress((void**)&h4, g_h4);

    cudaFuncSetAttribute(moe_fc3_kernel,
                         cudaFuncAttributeMaxDynamicSharedMemorySize,
                         MOE_SMEM_FLOATS * (int)sizeof(float));

    // weight pre-pass (independent of conv path)
    prep_w1<<<(64 * W1CH + 255) / 256, 256>>>(exp_w1);
    prep_w2<<<(64 * W2CH + 255) / 256, 256>>>(exp_w2);

    conv1_kernel<<<(B + 2) / 3, 608>>>(x, conv1_w, conv1_b, h1, B);
    conv2_kernel<<<(B + 2) / 3, 256>>>(h1, conv2_w, conv2_b, h2, B);

    dim3 g1(2, B / 64);
    gemm_bias_relu<<<g1, 256>>>(h2, fc1_w, fc1_b, h3, B, 120, 400, 1);
    dim3 g2(2, B / 64);
    gemm_bias_relu<<<g2, 256>>>(h3, fc2_w, fc2_b, h4, B, 84, 120, 1);

    moe_fc3_kernel<<<B / 128, 512, MOE_SMEM_FLOATS * (int)sizeof(float)>>>(
        h4, gate_w, exp_b1, exp_b2, fc3_w, fc3_b, out);
}

// round 13
// speedup vs baseline: 1.0156x; 1.0156x over previous
#include <cuda_runtime.h>
#include <math.h>
#include <stdint.h>

#define B_TOTAL 16384

// ---------------- scratch (device globals; no allocation allowed) ----------
__device__ float g_h1[B_TOTAL * 6 * 14 * 14];   // after conv1+relu+pool
__device__ float g_h2[B_TOTAL * 400];           // after conv2+relu+pool (flat)
__device__ float g_h3[B_TOTAL * 120];           // after fc1+relu
__device__ float g_h4[B_TOTAL * 84];            // after fc2+relu

// pre-converted tf32 expert weights, PAIRWISE layout for float2 B-frag loads:
// W1p: [cc][n=0..63][ks=0..10][tig=0..3][2]  value pair = w1[e][8ks+tig(+4)][c*64+n]
// W2p: [cc][d=0..95][hb=0..7][tig=0..3][2]   value pair = w2[e][c*64+8hb+tig(+4)][d]
#define W1CH 5632
#define W2CH 6912
__device__ float g_w1t[64 * W1CH];
__device__ float g_w2t[64 * W2CH];

// ---------------------------------------------------------------------------
// helpers
// ---------------------------------------------------------------------------
__device__ __forceinline__ float to_tf32(float f) {
    uint32_t u;
    asm("cvt.rna.tf32.f32 %0, %1;" : "=r"(u) : "f"(f));
    return __uint_as_float(u);
}

__device__ __forceinline__ void mma_tf32(float c[4],
                                         uint32_t a0, uint32_t a1, uint32_t a2, uint32_t a3,
                                         uint32_t b0, uint32_t b1) {
    asm volatile(
        "mma.sync.aligned.m16n8k8.row.col.f32.tf32.tf32.f32 "
        "{%0,%1,%2,%3}, {%4,%5,%6,%7}, {%8,%9}, {%0,%1,%2,%3};\n"
        : "+f"(c[0]), "+f"(c[1]), "+f"(c[2]), "+f"(c[3])
        : "r"(a0), "r"(a1), "r"(a2), "r"(a3), "r"(b0), "r"(b1));
}

#define CP16(dst, src) \
    asm volatile("cp.async.cg.shared.global [%0], [%1], 16;\n" \
                 :: "r"(dst), "l"(src))

// ---------------------------------------------------------------------------
// weight pre-pass kernels (pairwise repack + tf32 convert)
// ---------------------------------------------------------------------------
__global__ __launch_bounds__(256) void prep_w1(const float* __restrict__ w1)
{
    int idx = blockIdx.x * 256 + threadIdx.x;
    if (idx >= 64 * W1CH) return;
    int cc = idx / W1CH;
    int r  = idx % W1CH;
    int n  = r / 88;
    int q  = r % 88;
    int ks = q >> 3;
    int tig = (q & 7) >> 1;
    int h  = q & 1;
    int k  = ks * 8 + tig + h * 4;
    int e  = cc >> 5, c = cc & 31;
    float v = 0.f;
    if (k < 84) v = to_tf32(w1[((size_t)e * 84 + k) * 2048 + c * 64 + n]);
    g_w1t[idx] = v;
}

__global__ __launch_bounds__(256) void prep_w2(const float* __restrict__ w2)
{
    int idx = blockIdx.x * 256 + threadIdx.x;
    if (idx >= 64 * W2CH) return;
    int cc = idx / W2CH;
    int r  = idx % W2CH;
    int d  = r / 72;
    int q  = r % 72;
    float v = 0.f;
    if (q < 64) {
        int hb  = q >> 3;
        int tig = (q & 7) >> 1;
        int h   = q & 1;
        int kk  = hb * 8 + tig + h * 4;
        int e   = cc >> 5, c = cc & 31;
        if (d < 84) v = to_tf32(w2[((size_t)e * 2048 + c * 64 + kk) * 84 + d]);
    }
    g_w2t[idx] = v;
}

// ---------------------------------------------------------------------------
// conv1: x[B,3,32,32] -> relu(maxpool2(conv 5x5, 6ch)) -> [B,6,14,14]
// 4 images/block, 800 threads (25 warps, 784 active = 98%), 1 block/SM.
// Per-thread work identical to the proven scalar version.
// ---------------------------------------------------------------------------
__global__ __launch_bounds__(800, 1) void conv1_kernel(
    const float* __restrict__ x, const float* __restrict__ w,
    const float* __restrict__ b, float* __restrict__ out, int B)
{
    __shared__ float s_img[4 * 3072];
    __shared__ float s_w[450];
    __shared__ float s_b[8];

    int img0 = blockIdx.x * 4;
    int nimg = B - img0; if (nimg > 4) nimg = 4;
    int tid = threadIdx.x;

    for (int i = tid; i < 450; i += 800) s_w[i] = w[i];
    if (tid < 6) s_b[tid] = b[tid];
    {
        const float* src = x + (size_t)img0 * 3072;
        int total = nimg * 3072;
        for (int i = tid; i < total; i += 800) s_img[i] = src[i];
    }
    __syncthreads();

    if (tid >= nimg * 196) return;
    int img = tid / 196;
    int r   = tid % 196;
    int py = r / 14;
    int px = r % 14;

    float acc[24];
#pragma unroll
    for (int i = 0; i < 24; i++) acc[i] = 0.f;

#pragma unroll
    for (int ic = 0; ic < 3; ic++) {
        float p[36];
        const float* ib = s_img + img * 3072 + ic * 1024 + (2 * py) * 32 + 2 * px;
#pragma unroll
        for (int ry = 0; ry < 6; ry++)
#pragma unroll
            for (int rx = 0; rx < 6; rx++)
                p[ry * 6 + rx] = ib[ry * 32 + rx];
#pragma unroll
        for (int oc = 0; oc < 6; oc++) {
            float wr[25];
#pragma unroll
            for (int i = 0; i < 25; i++) wr[i] = s_w[oc * 75 + ic * 25 + i];
#pragma unroll
            for (int ky = 0; ky < 5; ky++)
#pragma unroll
                for (int kx = 0; kx < 5; kx++) {
                    float wv = wr[ky * 5 + kx];
                    acc[oc * 4 + 0] += p[ ky      * 6 + kx    ] * wv;
                    acc[oc * 4 + 1] += p[ ky      * 6 + kx + 1] * wv;
                    acc[oc * 4 + 2] += p[(ky + 1) * 6 + kx    ] * wv;
                    acc[oc * 4 + 3] += p[(ky + 1) * 6 + kx + 1] * wv;
                }
        }
    }

    float* ob = out + (size_t)(img0 + img) * 1176 + py * 14 + px;
#pragma unroll
    for (int oc = 0; oc < 6; oc++) {
        float m = fmaxf(fmaxf(acc[oc * 4 + 0], acc[oc * 4 + 1]),
                        fmaxf(acc[oc * 4 + 2], acc[oc * 4 + 3]));
        ob[oc * 196] = fmaxf(m + s_b[oc], 0.f);
    }
}

// ---------------------------------------------------------------------------
// conv2: h1[B,6,14,14] -> relu(maxpool2(conv 5x5, 16ch)) -> [B,16,5,5] flat 400
// ---------------------------------------------------------------------------
__global__ __launch_bounds__(256) void conv2_kernel(
    const float* __restrict__ in, const float* __restrict__ w,
    const float* __restrict__ b, float* __restrict__ out, int B)
{
    __shared__ float s_in[3 * 1176];
    __shared__ float s_w[2400];
    __shared__ float s_b[16];

    int img0 = blockIdx.x * 3;
    int nimg = B - img0; if (nimg > 3) nimg = 3;

    for (int i = threadIdx.x; i < 2400; i += 256) s_w[i] = w[i];
    if (threadIdx.x < 16) s_b[threadIdx.x] = b[threadIdx.x];
    {
        const float* src = in + (size_t)img0 * 1176;
        int total = nimg * 1176;
        for (int i = threadIdx.x; i < total; i += 256) s_in[i] = src[i];
    }
    __syncthreads();

    int t = threadIdx.x;
    if (t >= nimg * 80) return;
    int img = t / 80;
    int r   = t % 80;
    int oc  = r / 5;
    int py  = r % 5;

    float acc[20];
#pragma unroll
    for (int i = 0; i < 20; i++) acc[i] = 0.f;

#pragma unroll
    for (int ic = 0; ic < 6; ic++) {
        float wreg[25];
#pragma unroll
        for (int i = 0; i < 25; i++) wreg[i] = s_w[oc * 150 + ic * 25 + i];
        const float* ib = s_in + img * 1176 + ic * 196 + (2 * py) * 14;
#pragma unroll
        for (int px = 0; px < 5; px++) {
            float p[36];
#pragma unroll
            for (int ry = 0; ry < 6; ry++)
#pragma unroll
                for (int rx = 0; rx < 6; rx++)
                    p[ry * 6 + rx] = ib[ry * 14 + 2 * px + rx];
#pragma unroll
            for (int ky = 0; ky < 5; ky++)
#pragma unroll
                for (int kx = 0; kx < 5; kx++) {
                    float wv = wreg[ky * 5 + kx];
                    acc[px * 4 + 0] += p[ ky      * 6 + kx    ] * wv;
                    acc[px * 4 + 1] += p[ ky      * 6 + kx + 1] * wv;
                    acc[px * 4 + 2] += p[(ky + 1) * 6 + kx    ] * wv;
                    acc[px * 4 + 3] += p[(ky + 1) * 6 + kx + 1] * wv;
                }
        }
    }
    float bias = s_b[oc];
    float* obase = out + (size_t)(img0 + img) * 400 + oc * 25 + py * 5;
#pragma unroll
    for (int px = 0; px < 5; px++) {
        float m = fmaxf(fmaxf(acc[px * 4 + 0], acc[px * 4 + 1]),
                        fmaxf(acc[px * 4 + 2], acc[px * 4 + 3]));
        obase[px] = fmaxf(m + bias, 0.f);
    }
}

// ---------------------------------------------------------------------------
// Generic tiled GEMM: C[M,N] = act(A[M,K] @ W[K,N] + bias), 64x64x16 tiles.
// ---------------------------------------------------------------------------
__global__ __launch_bounds__(256) void gemm_bias_relu(
    const float* __restrict__ A, const float* __restrict__ W,
    const float* __restrict__ bias, float* __restrict__ C,
    int M, int N, int K, int doRelu)
{
    __shared__ float As[16][65];
    __shared__ float Ws[16][64];

    int n0 = blockIdx.x * 64;
    int m0 = blockIdx.y * 64;
    int tx = threadIdx.x & 15;
    int ty = threadIdx.x >> 4;

    float acc[4][4];
#pragma unroll
    for (int i = 0; i < 4; i++)
#pragma unroll
        for (int j = 0; j < 4; j++) acc[i][j] = 0.f;

    for (int k0 = 0; k0 < K; k0 += 16) {
#pragma unroll
        for (int q = 0; q < 4; q++) {
            int idx = threadIdx.x + q * 256;
            int m = idx >> 4, kk = idx & 15;
            int gk = k0 + kk;
            As[kk][m] = (gk < K) ? A[(size_t)(m0 + m) * K + gk] : 0.f;
        }
#pragma unroll
        for (int q = 0; q < 4; q++) {
            int idx = threadIdx.x + q * 256;
            int kk = idx >> 6, n = idx & 63;
            int gk = k0 + kk, gn = n0 + n;
            Ws[kk][n] = (gk < K && gn < N) ? W[(size_t)gk * N + gn] : 0.f;
        }
        __syncthreads();
#pragma unroll
        for (int kk = 0; kk < 16; kk++) {
            float a[4], bb[4];
#pragma unroll
            for (int i = 0; i < 4; i++) a[i] = As[kk][ty + 16 * i];
#pragma unroll
            for (int j = 0; j < 4; j++) bb[j] = Ws[kk][tx + 16 * j];
#pragma unroll
            for (int i = 0; i < 4; i++)
#pragma unroll
                for (int j = 0; j < 4; j++) acc[i][j] += a[i] * bb[j];
        }
        __syncthreads();
    }

#pragma unroll
    for (int i = 0; i < 4; i++) {
        int m = m0 + ty + 16 * i;
#pragma unroll
        for (int j = 0; j < 4; j++) {
            int n = n0 + tx + 16 * j;
            if (n < N && m < M) {
                float v = acc[i][j] + bias[n];
                if (doRelu) v = fmaxf(v, 0.f);
                C[(size_t)m * N + n] = v;
            }
        }
    }
}

// ---------------------------------------------------------------------------
// Fused MoE + fc3, tf32 mma. 128 tokens/block, 256 threads (8 warps).
// Warp owns 16 token rows end-to-end; H stays in registers (shuffle C->A).
// Pairwise weight layout -> float2 (LDS.64) B-fragment loads.
// X A-fragments hoisted to registers (loop-invariant).  (exact R11 version)
// ---------------------------------------------------------------------------
#define XS_STRIDE 92
// smem float offsets
#define OFF_X    0                                  // 128*92 = 11776
#define OFF_W1   (128 * XS_STRIDE)                  // 11776  (2 bufs x 5632)
#define OFF_W2   (OFF_W1 + 2 * W1CH)                // 23040  (2 bufs x 6912)
#define OFF_B1   (OFF_W2 + 2 * W2CH)                // 36864  (2 x 64)
#define OFF_GW   (OFF_B1 + 128)                     // 36992
#define OFF_C    (OFF_GW + 168)                     // 37160
#define OFF_B2   (OFF_C + 256)                      // 37416
#define OFF_W3   (OFF_B2 + 168)                     // 37584
#define OFF_B3   (OFF_W3 + 840)                     // 38424
#define MOE_SMEM_FLOATS (OFF_B3 + 16)               // 38440 (153.8 KB)

__global__ __launch_bounds__(256) void moe_fc3_kernel(
    const float* __restrict__ x,      // [B,84]
    const float* __restrict__ gate_w, // [84,2]
    const float* __restrict__ b1g,    // [2,2048]
    const float* __restrict__ b2,     // [2,84]
    const float* __restrict__ w3,     // [84,10]
    const float* __restrict__ b3,     // [10]
    float* __restrict__ out)          // [B,10]
{
    extern __shared__ float sm[];
    float* X_s  = sm + OFF_X;
    float* W1_s = sm + OFF_W1;
    float* W2_s = sm + OFF_W2;
    float* sb1  = sm + OFF_B1;
    float* sgw  = sm + OFF_GW;
    float* c_s  = sm + OFF_C;
    float* sb2  = sm + OFF_B2;
    float* sw3  = sm + OFF_W3;
    float* sb3  = sm + OFF_B3;

    const int tid = threadIdx.x;
    const int t0  = blockIdx.x * 128;

    const uint32_t smbase = (uint32_t)__cvta_generic_to_shared(sm);
    const uint32_t w1_sm  = smbase + OFF_W1 * 4;
    const uint32_t w2_sm  = smbase + OFF_W2 * 4;
    const uint32_t b1_sm  = smbase + OFF_B1 * 4;

    // ---- prologue: async-load chunk 0 weights into buffer 0 ----
    {
        const float4* s1 = (const float4*)(g_w1t);
        for (int i = tid; i < W1CH / 4; i += 256) CP16(w1_sm + i * 16, s1 + i);
        const float4* s2 = (const float4*)(g_w2t);
        for (int i = tid; i < W2CH / 4; i += 256) CP16(w2_sm + i * 16, s2 + i);
        if (tid < 16) CP16(b1_sm + tid * 16, (const float4*)b1g + tid);
    }
    asm volatile("cp.async.commit_group;\n" ::: "memory");

    // ---- sync loads: X + constants ----
    for (int i = tid; i < 128 * 84; i += 256) {
        int t = i / 84, k = i % 84;
        X_s[t * XS_STRIDE + k] = x[(size_t)(t0 + t) * 84 + k];
    }
    for (int i = tid; i < 128 * 8; i += 256) {
        int t = i / 8, k = 84 + (i % 8);
        X_s[t * XS_STRIDE + k] = 0.f;
    }
    for (int i = tid; i < 168; i += 256) sgw[i] = gate_w[i];
    for (int i = tid; i < 168; i += 256) sb2[i] = b2[i];
    for (int i = tid; i < 840; i += 256) sw3[i] = w3[i];
    if (tid < 10) sb3[tid] = b3[tid];
    __syncthreads();

    // ---- gate: softmax over 2 logits (top-2 of 2 + renorm == softmax) ----
    if (tid < 128) {
        float l0 = 0.f, l1 = 0.f;
        const float* xr = X_s + tid * XS_STRIDE;
#pragma unroll 4
        for (int k = 0; k < 84; k++) {
            l0 += xr[k] * sgw[k * 2 + 0];
            l1 += xr[k] * sgw[k * 2 + 1];
        }
        float m = fmaxf(l0, l1);
        float e0 = expf(l0 - m), e1 = expf(l1 - m);
        float inv = 1.f / (e0 + e1);
        c_s[tid * 2 + 0] = e0 * inv;
        c_s[tid * 2 + 1] = e1 * inv;
    }
    __syncthreads();

    // ---- convert X to tf32 in place ----
    for (int i = tid; i < 128 * XS_STRIDE; i += 256) X_s[i] = to_tf32(X_s[i]);
    __syncthreads();

    const int lane = tid & 31, wid = tid >> 5;
    const int gid = lane >> 2, tig = lane & 3;
    const int wm  = wid * 16;                  // warp owns rows [wm, wm+16)
    const int L0  = (lane & 0x1C) + (tig >> 1);  // shuffle src for cols t
    const int L2  = L0 + 2;                      // shuffle src for cols t+4
    const bool odd = (tig & 1);

    // per-row gates (loop-invariant)
    const float gA0 = c_s[(wm + gid    ) * 2 + 0];
    const float gA1 = c_s[(wm + gid    ) * 2 + 1];
    const float gB0 = c_s[(wm + gid + 8) * 2 + 0];
    const float gB1 = c_s[(wm + gid + 8) * 2 + 1];

    // ---- hoist X A-fragments (loop-invariant over all 64 chunks) ----
    uint32_t XA[11][4];
#pragma unroll
    for (int ks = 0; ks < 11; ks++) {
        int k = ks * 8 + tig;
        XA[ks][0] = __float_as_uint(X_s[(wm + gid    ) * XS_STRIDE + k    ]);
        XA[ks][1] = __float_as_uint(X_s[(wm + gid + 8) * XS_STRIDE + k    ]);
        XA[ks][2] = __float_as_uint(X_s[(wm + gid    ) * XS_STRIDE + k + 4]);
        XA[ks][3] = __float_as_uint(X_s[(wm + gid + 8) * XS_STRIDE + k + 4]);
    }

    float accY[12][4];
#pragma unroll
    for (int nb = 0; nb < 12; nb++)
#pragma unroll
        for (int r = 0; r < 4; r++) accY[nb][r] = 0.f;

    for (int cc = 0; cc < 64; cc++) {
        const int buf = cc & 1;
        const int e   = cc >> 5;

        asm volatile("cp.async.wait_group 0;\n" ::: "memory");
        __syncthreads();   // weights for chunk cc resident; prior chunk done

        // prefetch chunk cc+1 into the other buffer
        if (cc + 1 < 64) {
            const int nb2 = buf ^ 1;
            const float4* s1 = (const float4*)(g_w1t + (size_t)(cc + 1) * W1CH);
            uint32_t d1 = w1_sm + nb2 * (W1CH * 4);
            for (int i = tid; i < W1CH / 4; i += 256) CP16(d1 + i * 16, s1 + i);
            const float4* s2 = (const float4*)(g_w2t + (size_t)(cc + 1) * W2CH);
            uint32_t d2 = w2_sm + nb2 * (W2CH * 4);
            for (int i = tid; i < W2CH / 4; i += 256) CP16(d2 + i * 16, s2 + i);
            if (tid < 16)
                CP16(b1_sm + nb2 * 256 + tid * 16,
                     (const float4*)(b1g + (size_t)(cc + 1) * 64) + tid);
        }
        asm volatile("cp.async.commit_group;\n" ::: "memory");

        const float2* W1b = (const float2*)(W1_s + buf * W1CH);
        const float2* W2b = (const float2*)(W2_s + buf * W2CH);
        const float* b1b = sb1 + buf * 64;

        const float gl = e ? gA1 : gA0;   // gate for rows wm+gid
        const float gh = e ? gB1 : gB0;   // gate for rows wm+gid+8

        // ---- GEMM1: accA = X(16x88) @ W1(88x64), full-width warp tile ----
        float accA[8][4];
#pragma unroll
        for (int nb = 0; nb < 8; nb++)
#pragma unroll
            for (int r = 0; r < 4; r++) accA[nb][r] = 0.f;

#pragma unroll
        for (int ks = 0; ks < 11; ks++) {
#pragma unroll
            for (int nb = 0; nb < 8; nb++) {
                int n = nb * 8 + gid;
                float2 bp = W1b[n * 44 + ks * 4 + tig];
                mma_tf32(accA[nb], XA[ks][0], XA[ks][1], XA[ks][2], XA[ks][3],
                         __float_as_uint(bp.x), __float_as_uint(bp.y));
            }
        }

        // ---- epilogue (regs) + GEMM2, per 8-col H block (k-block hb) ----
#pragma unroll
        for (int hb = 0; hb < 8; hb++) {
            int n0 = hb * 8 + 2 * tig;
            float ba = b1b[n0], bbv = b1b[n0 + 1];
            float h0 = to_tf32(fmaxf(accA[hb][0] + ba , 0.f) * gl);
            float h1 = to_tf32(fmaxf(accA[hb][1] + bbv, 0.f) * gl);
            float h2 = to_tf32(fmaxf(accA[hb][2] + ba , 0.f) * gh);
            float h3 = to_tf32(fmaxf(accA[hb][3] + bbv, 0.f) * gh);

            // shuffle C-frag -> A-frag
            float u0 = __shfl_sync(0xFFFFFFFFu, h0, L0);
            float u1 = __shfl_sync(0xFFFFFFFFu, h1, L0);
            float u2 = __shfl_sync(0xFFFFFFFFu, h2, L0);
            float u3 = __shfl_sync(0xFFFFFFFFu, h3, L0);
            float v0 = __shfl_sync(0xFFFFFFFFu, h0, L2);
            float v1 = __shfl_sync(0xFFFFFFFFu, h1, L2);
            float v2 = __shfl_sync(0xFFFFFFFFu, h2, L2);
            float v3 = __shfl_sync(0xFFFFFFFFu, h3, L2);
            uint32_t a0 = __float_as_uint(odd ? u1 : u0);
            uint32_t a1 = __float_as_uint(odd ? u3 : u2);
            uint32_t a2 = __float_as_uint(odd ? v1 : v0);
            uint32_t a3 = __float_as_uint(odd ? v3 : v2);

#pragma unroll
            for (int nb = 0; nb < 12; nb++) {
                int n = nb * 8 + gid;
                float2 bp = W2b[n * 36 + hb * 4 + tig];
                mma_tf32(accY[nb], a0, a1, a2, a3,
                         __float_as_uint(bp.x), __float_as_uint(bp.y));
            }
        }
    }

    // ---- Y = accY + combined b2 -> Y_s (reuse W1_s area), then fc3 ----
    __syncthreads();   // all warps done with final chunk's weights
    float* Y_s = W1_s;   // 2*5632 = 11264 >= 128*84 = 10752
    {
#pragma unroll
        for (int nb = 0; nb < 12; nb++) {
            int d = nb * 8 + 2 * tig;
            if (d < 84) {
                float bc = gA0 * sb2[d] + gA1 * sb2[84 + d];
                float bh = gB0 * sb2[d] + gB1 * sb2[84 + d];
                Y_s[(wm + gid    ) * 84 + d] = accY[nb][0] + bc;
                Y_s[(wm + gid + 8) * 84 + d] = accY[nb][2] + bh;
            }
            if (d + 1 < 84) {
                float bc = gA0 * sb2[d + 1] + gA1 * sb2[84 + d + 1];
                float bh = gB0 * sb2[d + 1] + gB1 * sb2[84 + d + 1];
                Y_s[(wm + gid    ) * 84 + d + 1] = accY[nb][1] + bc;
                Y_s[(wm + gid + 8) * 84 + d + 1] = accY[nb][3] + bh;
            }
        }
    }
    __syncthreads();

    // fc3: [128,84] @ [84,10] + b3
    for (int o = tid; o < 1280; o += 256) {
        int t = o / 10, cc = o % 10;
        float s = sb3[cc];
        const float* yr = Y_s + t * 84;
#pragma unroll 4
        for (int d = 0; d < 84; d++) s += yr[d] * sw3[d * 10 + cc];
        out[(size_t)(t0 + t) * 10 + cc] = s;
    }
}

// ---------------------------------------------------------------------------
extern "C" void kernel_launch(void* const* d_in, const int* in_sizes, int n_in,
                              void* d_out, int out_size)
{
    const float* x       = (const float*)d_in[0];
    const float* conv1_w = (const float*)d_in[1];
    const float* conv1_b = (const float*)d_in[2];
    const float* conv2_w = (const float*)d_in[3];
    const float* conv2_b = (const float*)d_in[4];
    const float* fc1_w   = (const float*)d_in[5];
    const float* fc1_b   = (const float*)d_in[6];
    const float* fc2_w   = (const float*)d_in[7];
    const float* fc2_b   = (const float*)d_in[8];
    const float* gate_w  = (const float*)d_in[9];
    const float* exp_w1  = (const float*)d_in[10];
    const float* exp_b1  = (const float*)d_in[11];
    const float* exp_w2  = (const float*)d_in[12];
    const float* exp_b2  = (const float*)d_in[13];
    const float* fc3_w   = (const float*)d_in[14];
    const float* fc3_b   = (const float*)d_in[15];
    float* out = (float*)d_out;

    const int B = B_TOTAL;

    float *h1, *h2, *h3, *h4;
    cudaGetSymbolAddress((void**)&h1, g_h1);
    cudaGetSymbolAddress((void**)&h2, g_h2);
    cudaGetSymbolAddress((void**)&h3, g_h3);
    cudaGetSymbolAddress((void**)&h4, g_h4);

    cudaFuncSetAttribute(moe_fc3_kernel,
                         cudaFuncAttributeMaxDynamicSharedMemorySize,
                         MOE_SMEM_FLOATS * (int)sizeof(float));

    // weight pre-pass (independent of conv path)
    prep_w1<<<(64 * W1CH + 255) / 256, 256>>>(exp_w1);
    prep_w2<<<(64 * W2CH + 255) / 256, 256>>>(exp_w2);

    conv1_kernel<<<(B + 3) / 4, 800>>>(x, conv1_w, conv1_b, h1, B);
    conv2_kernel<<<(B + 2) / 3, 256>>>(h1, conv2_w, conv2_b, h2, B);

    dim3 g1(2, B / 64);
    gemm_bias_relu<<<g1, 256>>>(h2, fc1_w, fc1_b, h3, B, 120, 400, 1);
    dim3 g2(2, B / 64);
    gemm_bias_relu<<<g2, 256>>>(h3, fc2_w, fc2_b, h4, B, 84, 120, 1);

    moe_fc3_kernel<<<B / 128, 256, MOE_SMEM_FLOATS * (int)sizeof(float)>>>(
        h4, gate_w, exp_b1, exp_b2, fc3_w, fc3_b, out);
}

// round 14
// speedup vs baseline: 1.0557x; 1.0395x over previous
#include <cuda_runtime.h>
#include <math.h>
#include <stdint.h>

#define B_TOTAL 16384

// ---------------- scratch (device globals; no allocation allowed) ----------
__device__ float g_h1[B_TOTAL * 6 * 14 * 14];   // after conv1+relu+pool
__device__ float g_h2[B_TOTAL * 400];           // after conv2+relu+pool (flat)
__device__ float g_h3[B_TOTAL * 120];           // after fc1+relu
__device__ float g_h4[B_TOTAL * 84];            // after fc2+relu

// pre-converted tf32 expert weights, PAIRWISE layout for float2 B-frag loads:
#define W1CH 5632
#define W2CH 6912
__device__ float g_w1t[64 * W1CH];
__device__ float g_w2t[64 * W2CH];

// ---------------------------------------------------------------------------
// helpers
// ---------------------------------------------------------------------------
__device__ __forceinline__ float to_tf32(float f) {
    uint32_t u;
    asm("cvt.rna.tf32.f32 %0, %1;" : "=r"(u) : "f"(f));
    return __uint_as_float(u);
}

__device__ __forceinline__ void mma_tf32(float c[4],
                                         uint32_t a0, uint32_t a1, uint32_t a2, uint32_t a3,
                                         uint32_t b0, uint32_t b1) {
    asm volatile(
        "mma.sync.aligned.m16n8k8.row.col.f32.tf32.tf32.f32 "
        "{%0,%1,%2,%3}, {%4,%5,%6,%7}, {%8,%9}, {%0,%1,%2,%3};\n"
        : "+f"(c[0]), "+f"(c[1]), "+f"(c[2]), "+f"(c[3])
        : "r"(a0), "r"(a1), "r"(a2), "r"(a3), "r"(b0), "r"(b1));
}

#define CP16(dst, src) \
    asm volatile("cp.async.cg.shared.global [%0], [%1], 16;\n" \
                 :: "r"(dst), "l"(src))

// ---------------------------------------------------------------------------
// weight pre-pass kernels (pairwise repack + tf32 convert)
// ---------------------------------------------------------------------------
__global__ __launch_bounds__(256) void prep_w1(const float* __restrict__ w1)
{
    int idx = blockIdx.x * 256 + threadIdx.x;
    if (idx >= 64 * W1CH) return;
    int cc = idx / W1CH;
    int r  = idx % W1CH;
    int n  = r / 88;
    int q  = r % 88;
    int ks = q >> 3;
    int tig = (q & 7) >> 1;
    int h  = q & 1;
    int k  = ks * 8 + tig + h * 4;
    int e  = cc >> 5, c = cc & 31;
    float v = 0.f;
    if (k < 84) v = to_tf32(w1[((size_t)e * 84 + k) * 2048 + c * 64 + n]);
    g_w1t[idx] = v;
}

__global__ __launch_bounds__(256) void prep_w2(const float* __restrict__ w2)
{
    int idx = blockIdx.x * 256 + threadIdx.x;
    if (idx >= 64 * W2CH) return;
    int cc = idx / W2CH;
    int r  = idx % W2CH;
    int d  = r / 72;
    int q  = r % 72;
    float v = 0.f;
    if (q < 64) {
        int hb  = q >> 3;
        int tig = (q & 7) >> 1;
        int h   = q & 1;
        int kk  = hb * 8 + tig + h * 4;
        int e   = cc >> 5, c = cc & 31;
        if (d < 84) v = to_tf32(w2[((size_t)e * 2048 + c * 64 + kk) * 84 + d]);
    }
    g_w2t[idx] = v;
}

// ---------------------------------------------------------------------------
// conv1 (tensor core): x[B,3,32,32] -> relu(maxpool2(conv5x5,6ch)) -> [B,6,14,14]
// Implicit-im2col tf32 mma: M = 2*784 conv positions, N = 8 (6 oc), K = 80
// (75 + pad; padded K has W=0 so A may read any in-bounds value).
// B-fragments (weights) held in 20 registers for the whole kernel.
// Conv outputs staged in smem [pos][9] (stride 9 -> conflict-free pooling),
// then pooled (max+bias+relu) to global.
// ---------------------------------------------------------------------------
#define C1_IMG   3072            // floats per image in smem
#define C1_CONV  (784 * 9)       // conv outputs per image (stride 9)
#define C1_OFF_IMG   0                       // 2 * 3072
#define C1_OFF_WB    (2 * C1_IMG)            // 320 float2 = 640 floats
#define C1_OFF_CONV  (C1_OFF_WB + 640)       // 2 * 7056
#define C1_OFF_B     (C1_OFF_CONV + 2 * C1_CONV)
#define C1_SMEM_FLOATS (C1_OFF_B + 8)

__global__ __launch_bounds__(256) void conv1_kernel(
    const float* __restrict__ x, const float* __restrict__ w,
    const float* __restrict__ b, float* __restrict__ out)
{
    extern __shared__ float c1sm[];
    float*  s_img  = c1sm + C1_OFF_IMG;     // [2][3072]
    float2* s_wB   = (float2*)(c1sm + C1_OFF_WB);   // [10][32]
    float*  s_conv = c1sm + C1_OFF_CONV;    // [2][784*9]
    float*  s_b    = c1sm + C1_OFF_B;

    const int img0 = blockIdx.x * 2;
    const int tid  = threadIdx.x;
    const int lane = tid & 31, wid = tid >> 5;
    const int gid  = lane >> 2, tig = lane & 3;

    // weights -> B-fragment pairs in smem: s_wB[ks*32+lane] = {W(8ks+tig, gid), W(8ks+tig+4, gid)}
    for (int i = tid; i < 320; i += 256) {
        int ks = i >> 5, l = i & 31;
        int g = l >> 2, t = l & 3;
        int k0 = ks * 8 + t, k1 = k0 + 4;
        float w0 = (k0 < 75 && g < 6) ? w[g * 75 + k0] : 0.f;
        float w1 = (k1 < 75 && g < 6) ? w[g * 75 + k1] : 0.f;
        s_wB[i] = make_float2(to_tf32(w0), to_tf32(w1));
    }
    if (tid < 8) s_b[tid] = (tid < 6) ? b[tid] : 0.f;
    for (int i = tid; i < 2 * C1_IMG; i += 256)
        s_img[i] = to_tf32(x[(size_t)img0 * C1_IMG + i]);
    __syncthreads();

    // hoist B fragments to registers
    uint32_t B0[10], B1[10];
#pragma unroll
    for (int ks = 0; ks < 10; ks++) {
        float2 p = s_wB[ks * 32 + lane];
        B0[ks] = __float_as_uint(p.x);
        B1[ks] = __float_as_uint(p.y);
    }
    // per-thread K offsets (ic*1024 + ky*32 + kx); padded k -> any safe addr (W=0)
    int off0[10], off4[10];
#pragma unroll
    for (int ks = 0; ks < 10; ks++) {
        int k = ks * 8 + tig;
        int kk = (k < 75) ? k : 0;
        off0[ks] = (kk / 25) * 1024 + ((kk % 25) / 5) * 32 + (kk % 5);
        k += 4; kk = (k < 75) ? k : 0;
        off4[ks] = (kk / 25) * 1024 + ((kk % 25) / 5) * 32 + (kk % 5);
    }

    // conv via mma: 98 m16-tiles (2 images x 49)
    for (int t = wid; t < 98; t += 8) {
        int img  = t / 49, tile = t % 49;
        int m_lo = tile * 16 + gid;
        int m_hi = m_lo + 8;
        const float* ib = s_img + img * C1_IMG;
        int p_lo = (m_lo / 28) * 32 + (m_lo % 28);
        int p_hi = (m_hi / 28) * 32 + (m_hi % 28);
        float c[4] = {0.f, 0.f, 0.f, 0.f};
#pragma unroll
        for (int ks = 0; ks < 10; ks++) {
            uint32_t a0 = __float_as_uint(ib[p_lo + off0[ks]]);
            uint32_t a1 = __float_as_uint(ib[p_hi + off0[ks]]);
            uint32_t a2 = __float_as_uint(ib[p_lo + off4[ks]]);
            uint32_t a3 = __float_as_uint(ib[p_hi + off4[ks]]);
            mma_tf32(c, a0, a1, a2, a3, B0[ks], B1[ks]);
        }
        float* sc = s_conv + img * C1_CONV;
        sc[m_lo * 9 + 2 * tig    ] = c[0];
        sc[m_lo * 9 + 2 * tig + 1] = c[1];
        sc[m_hi * 9 + 2 * tig    ] = c[2];
        sc[m_hi * 9 + 2 * tig + 1] = c[3];
    }
    __syncthreads();

    // pooling: 2 img x 6 oc x 14x14
    for (int o = tid; o < 2352; o += 256) {
        int img = o / 1176;
        int r   = o % 1176;
        int oc  = r / 196;
        int pp  = r % 196;
        int py = pp / 14, px = pp % 14;
        const float* sc = s_conv + img * C1_CONV;
        int q0 = (2 * py) * 28 + 2 * px;
        float v = fmaxf(fmaxf(sc[ q0       * 9 + oc], sc[(q0 +  1) * 9 + oc]),
                        fmaxf(sc[(q0 + 28) * 9 + oc], sc[(q0 + 29) * 9 + oc]));
        out[(size_t)(img0 + img) * 1176 + oc * 196 + pp] = fmaxf(v + s_b[oc], 0.f);
    }
}

// ---------------------------------------------------------------------------
// conv2: h1[B,6,14,14] -> relu(maxpool2(conv 5x5, 16ch)) -> [B,16,5,5] flat 400
// ---------------------------------------------------------------------------
__global__ __launch_bounds__(256) void conv2_kernel(
    const float* __restrict__ in, const float* __restrict__ w,
    const float* __restrict__ b, float* __restrict__ out, int B)
{
    __shared__ float s_in[3 * 1176];
    __shared__ float s_w[2400];
    __shared__ float s_b[16];

    int img0 = blockIdx.x * 3;
    int nimg = B - img0; if (nimg > 3) nimg = 3;

    for (int i = threadIdx.x; i < 2400; i += 256) s_w[i] = w[i];
    if (threadIdx.x < 16) s_b[threadIdx.x] = b[threadIdx.x];
    {
        const float* src = in + (size_t)img0 * 1176;
        int total = nimg * 1176;
        for (int i = threadIdx.x; i < total; i += 256) s_in[i] = src[i];
    }
    __syncthreads();

    int t = threadIdx.x;
    if (t >= nimg * 80) return;
    int img = t / 80;
    int r   = t % 80;
    int oc  = r / 5;
    int py  = r % 5;

    float acc[20];
#pragma unroll
    for (int i = 0; i < 20; i++) acc[i] = 0.f;

#pragma unroll
    for (int ic = 0; ic < 6; ic++) {
        float wreg[25];
#pragma unroll
        for (int i = 0; i < 25; i++) wreg[i] = s_w[oc * 150 + ic * 25 + i];
        const float* ib = s_in + img * 1176 + ic * 196 + (2 * py) * 14;
#pragma unroll
        for (int px = 0; px < 5; px++) {
            float p[36];
#pragma unroll
            for (int ry = 0; ry < 6; ry++)
#pragma unroll
                for (int rx = 0; rx < 6; rx++)
                    p[ry * 6 + rx] = ib[ry * 14 + 2 * px + rx];
#pragma unroll
            for (int ky = 0; ky < 5; ky++)
#pragma unroll
                for (int kx = 0; kx < 5; kx++) {
                    float wv = wreg[ky * 5 + kx];
                    acc[px * 4 + 0] += p[ ky      * 6 + kx    ] * wv;
                    acc[px * 4 + 1] += p[ ky      * 6 + kx + 1] * wv;
                    acc[px * 4 + 2] += p[(ky + 1) * 6 + kx    ] * wv;
                    acc[px * 4 + 3] += p[(ky + 1) * 6 + kx + 1] * wv;
                }
        }
    }
    float bias = s_b[oc];
    float* obase = out + (size_t)(img0 + img) * 400 + oc * 25 + py * 5;
#pragma unroll
    for (int px = 0; px < 5; px++) {
        float m = fmaxf(fmaxf(acc[px * 4 + 0], acc[px * 4 + 1]),
                        fmaxf(acc[px * 4 + 2], acc[px * 4 + 3]));
        obase[px] = fmaxf(m + bias, 0.f);
    }
}

// ---------------------------------------------------------------------------
// Generic tiled GEMM: C[M,N] = act(A[M,K] @ W[K,N] + bias), 64x64x16 tiles.
// ---------------------------------------------------------------------------
__global__ __launch_bounds__(256) void gemm_bias_relu(
    const float* __restrict__ A, const float* __restrict__ W,
    const float* __restrict__ bias, float* __restrict__ C,
    int M, int N, int K, int doRelu)
{
    __shared__ float As[16][65];
    __shared__ float Ws[16][64];

    int n0 = blockIdx.x * 64;
    int m0 = blockIdx.y * 64;
    int tx = threadIdx.x & 15;
    int ty = threadIdx.x >> 4;

    float acc[4][4];
#pragma unroll
    for (int i = 0; i < 4; i++)
#pragma unroll
        for (int j = 0; j < 4; j++) acc[i][j] = 0.f;

    for (int k0 = 0; k0 < K; k0 += 16) {
#pragma unroll
        for (int q = 0; q < 4; q++) {
            int idx = threadIdx.x + q * 256;
            int m = idx >> 4, kk = idx & 15;
            int gk = k0 + kk;
            As[kk][m] = (gk < K) ? A[(size_t)(m0 + m) * K + gk] : 0.f;
        }
#pragma unroll
        for (int q = 0; q < 4; q++) {
            int idx = threadIdx.x + q * 256;
            int kk = idx >> 6, n = idx & 63;
            int gk = k0 + kk, gn = n0 + n;
            Ws[kk][n] = (gk < K && gn < N) ? W[(size_t)gk * N + gn] : 0.f;
        }
        __syncthreads();
#pragma unroll
        for (int kk = 0; kk < 16; kk++) {
            float a[4], bb[4];
#pragma unroll
            for (int i = 0; i < 4; i++) a[i] = As[kk][ty + 16 * i];
#pragma unroll
            for (int j = 0; j < 4; j++) bb[j] = Ws[kk][tx + 16 * j];
#pragma unroll
            for (int i = 0; i < 4; i++)
#pragma unroll
                for (int j = 0; j < 4; j++) acc[i][j] += a[i] * bb[j];
        }
        __syncthreads();
    }

#pragma unroll
    for (int i = 0; i < 4; i++) {
        int m = m0 + ty + 16 * i;
#pragma unroll
        for (int j = 0; j < 4; j++) {
            int n = n0 + tx + 16 * j;
            if (n < N && m < M) {
                float v = acc[i][j] + bias[n];
                if (doRelu) v = fmaxf(v, 0.f);
                C[(size_t)m * N + n] = v;
            }
        }
    }
}

// ---------------------------------------------------------------------------
// Fused MoE + fc3, tf32 mma. 128 tokens/block, 256 threads (8 warps).
// (exact R11/R13 version — best measured)
// ---------------------------------------------------------------------------
#define XS_STRIDE 92
#define OFF_X    0
#define OFF_W1   (128 * XS_STRIDE)
#define OFF_W2   (OFF_W1 + 2 * W1CH)
#define OFF_B1   (OFF_W2 + 2 * W2CH)
#define OFF_GW   (OFF_B1 + 128)
#define OFF_C    (OFF_GW + 168)
#define OFF_B2   (OFF_C + 256)
#define OFF_W3   (OFF_B2 + 168)
#define OFF_B3   (OFF_W3 + 840)
#define MOE_SMEM_FLOATS (OFF_B3 + 16)

__global__ __launch_bounds__(256) void moe_fc3_kernel(
    const float* __restrict__ x,
    const float* __restrict__ gate_w,
    const float* __restrict__ b1g,
    const float* __restrict__ b2,
    const float* __restrict__ w3,
    const float* __restrict__ b3,
    float* __restrict__ out)
{
    extern __shared__ float sm[];
    float* X_s  = sm + OFF_X;
    float* W1_s = sm + OFF_W1;
    float* W2_s = sm + OFF_W2;
    float* sb1  = sm + OFF_B1;
    float* sgw  = sm + OFF_GW;
    float* c_s  = sm + OFF_C;
    float* sb2  = sm + OFF_B2;
    float* sw3  = sm + OFF_W3;
    float* sb3  = sm + OFF_B3;

    const int tid = threadIdx.x;
    const int t0  = blockIdx.x * 128;

    const uint32_t smbase = (uint32_t)__cvta_generic_to_shared(sm);
    const uint32_t w1_sm  = smbase + OFF_W1 * 4;
    const uint32_t w2_sm  = smbase + OFF_W2 * 4;
    const uint32_t b1_sm  = smbase + OFF_B1 * 4;

    {
        const float4* s1 = (const float4*)(g_w1t);
        for (int i = tid; i < W1CH / 4; i += 256) CP16(w1_sm + i * 16, s1 + i);
        const float4* s2 = (const float4*)(g_w2t);
        for (int i = tid; i < W2CH / 4; i += 256) CP16(w2_sm + i * 16, s2 + i);
        if (tid < 16) CP16(b1_sm + tid * 16, (const float4*)b1g + tid);
    }
    asm volatile("cp.async.commit_group;\n" ::: "memory");

    for (int i = tid; i < 128 * 84; i += 256) {
        int t = i / 84, k = i % 84;
        X_s[t * XS_STRIDE + k] = x[(size_t)(t0 + t) * 84 + k];
    }
    for (int i = tid; i < 128 * 8; i += 256) {
        int t = i / 8, k = 84 + (i % 8);
        X_s[t * XS_STRIDE + k] = 0.f;
    }
    for (int i = tid; i < 168; i += 256) sgw[i] = gate_w[i];
    for (int i = tid; i < 168; i += 256) sb2[i] = b2[i];
    for (int i = tid; i < 840; i += 256) sw3[i] = w3[i];
    if (tid < 10) sb3[tid] = b3[tid];
    __syncthreads();

    if (tid < 128) {
        float l0 = 0.f, l1 = 0.f;
        const float* xr = X_s + tid * XS_STRIDE;
#pragma unroll 4
        for (int k = 0; k < 84; k++) {
            l0 += xr[k] * sgw[k * 2 + 0];
            l1 += xr[k] * sgw[k * 2 + 1];
        }
        float m = fmaxf(l0, l1);
        float e0 = expf(l0 - m), e1 = expf(l1 - m);
        float inv = 1.f / (e0 + e1);
        c_s[tid * 2 + 0] = e0 * inv;
        c_s[tid * 2 + 1] = e1 * inv;
    }
    __syncthreads();

    for (int i = tid; i < 128 * XS_STRIDE; i += 256) X_s[i] = to_tf32(X_s[i]);
    __syncthreads();

    const int lane = tid & 31, wid = tid >> 5;
    const int gid = lane >> 2, tig = lane & 3;
    const int wm  = wid * 16;
    const int L0  = (lane & 0x1C) + (tig >> 1);
    const int L2  = L0 + 2;
    const bool odd = (tig & 1);

    const float gA0 = c_s[(wm + gid    ) * 2 + 0];
    const float gA1 = c_s[(wm + gid    ) * 2 + 1];
    const float gB0 = c_s[(wm + gid + 8) * 2 + 0];
    const float gB1 = c_s[(wm + gid + 8) * 2 + 1];

    uint32_t XA[11][4];
#pragma unroll
    for (int ks = 0; ks < 11; ks++) {
        int k = ks * 8 + tig;
        XA[ks][0] = __float_as_uint(X_s[(wm + gid    ) * XS_STRIDE + k    ]);
        XA[ks][1] = __float_as_uint(X_s[(wm + gid + 8) * XS_STRIDE + k    ]);
        XA[ks][2] = __float_as_uint(X_s[(wm + gid    ) * XS_STRIDE + k + 4]);
        XA[ks][3] = __float_as_uint(X_s[(wm + gid + 8) * XS_STRIDE + k + 4]);
    }

    float accY[12][4];
#pragma unroll
    for (int nb = 0; nb < 12; nb++)
#pragma unroll
        for (int r = 0; r < 4; r++) accY[nb][r] = 0.f;

    for (int cc = 0; cc < 64; cc++) {
        const int buf = cc & 1;
        const int e   = cc >> 5;

        asm volatile("cp.async.wait_group 0;\n" ::: "memory");
        __syncthreads();

        if (cc + 1 < 64) {
            const int nb2 = buf ^ 1;
            const float4* s1 = (const float4*)(g_w1t + (size_t)(cc + 1) * W1CH);
            uint32_t d1 = w1_sm + nb2 * (W1CH * 4);
            for (int i = tid; i < W1CH / 4; i += 256) CP16(d1 + i * 16, s1 + i);
            const float4* s2 = (const float4*)(g_w2t + (size_t)(cc + 1) * W2CH);
            uint32_t d2 = w2_sm + nb2 * (W2CH * 4);
            for (int i = tid; i < W2CH / 4; i += 256) CP16(d2 + i * 16, s2 + i);
            if (tid < 16)
                CP16(b1_sm + nb2 * 256 + tid * 16,
                     (const float4*)(b1g + (size_t)(cc + 1) * 64) + tid);
        }
        asm volatile("cp.async.commit_group;\n" ::: "memory");

        const float2* W1b = (const float2*)(W1_s + buf * W1CH);
        const float2* W2b = (const float2*)(W2_s + buf * W2CH);
        const float* b1b = sb1 + buf * 64;

        const float gl = e ? gA1 : gA0;
        const float gh = e ? gB1 : gB0;

        float accA[8][4];
#pragma unroll
        for (int nb = 0; nb < 8; nb++)
#pragma unroll
            for (int r = 0; r < 4; r++) accA[nb][r] = 0.f;

#pragma unroll
        for (int ks = 0; ks < 11; ks++) {
#pragma unroll
            for (int nb = 0; nb < 8; nb++) {
                int n = nb * 8 + gid;
                float2 bp = W1b[n * 44 + ks * 4 + tig];
                mma_tf32(accA[nb], XA[ks][0], XA[ks][1], XA[ks][2], XA[ks][3],
                         __float_as_uint(bp.x), __float_as_uint(bp.y));
            }
        }

#pragma unroll
        for (int hb = 0; hb < 8; hb++) {
            int n0 = hb * 8 + 2 * tig;
            float ba = b1b[n0], bbv = b1b[n0 + 1];
            float h0 = to_tf32(fmaxf(accA[hb][0] + ba , 0.f) * gl);
            float h1 = to_tf32(fmaxf(accA[hb][1] + bbv, 0.f) * gl);
            float h2 = to_tf32(fmaxf(accA[hb][2] + ba , 0.f) * gh);
            float h3 = to_tf32(fmaxf(accA[hb][3] + bbv, 0.f) * gh);

            float u0 = __shfl_sync(0xFFFFFFFFu, h0, L0);
            float u1 = __shfl_sync(0xFFFFFFFFu, h1, L0);
            float u2 = __shfl_sync(0xFFFFFFFFu, h2, L0);
            float u3 = __shfl_sync(0xFFFFFFFFu, h3, L0);
            float v0 = __shfl_sync(0xFFFFFFFFu, h0, L2);
            float v1 = __shfl_sync(0xFFFFFFFFu, h1, L2);
            float v2 = __shfl_sync(0xFFFFFFFFu, h2, L2);
            float v3 = __shfl_sync(0xFFFFFFFFu, h3, L2);
            uint32_t a0 = __float_as_uint(odd ? u1 : u0);
            uint32_t a1 = __float_as_uint(odd ? u3 : u2);
            uint32_t a2 = __float_as_uint(odd ? v1 : v0);
            uint32_t a3 = __float_as_uint(odd ? v3 : v2);

#pragma unroll
            for (int nb = 0; nb < 12; nb++) {
                int n = nb * 8 + gid;
                float2 bp = W2b[n * 36 + hb * 4 + tig];
                mma_tf32(accY[nb], a0, a1, a2, a3,
                         __float_as_uint(bp.x), __float_as_uint(bp.y));
            }
        }
    }

    __syncthreads();
    float* Y_s = W1_s;
    {
#pragma unroll
        for (int nb = 0; nb < 12; nb++) {
            int d = nb * 8 + 2 * tig;
            if (d < 84) {
                float bc = gA0 * sb2[d] + gA1 * sb2[84 + d];
                float bh = gB0 * sb2[d] + gB1 * sb2[84 + d];
                Y_s[(wm + gid    ) * 84 + d] = accY[nb][0] + bc;
                Y_s[(wm + gid + 8) * 84 + d] = accY[nb][2] + bh;
            }
            if (d + 1 < 84) {
                float bc = gA0 * sb2[d + 1] + gA1 * sb2[84 + d + 1];
                float bh = gB0 * sb2[d + 1] + gB1 * sb2[84 + d + 1];
                Y_s[(wm + gid    ) * 84 + d + 1] = accY[nb][1] + bc;
                Y_s[(wm + gid + 8) * 84 + d + 1] = accY[nb][3] + bh;
            }
        }
    }
    __syncthreads();

    for (int o = tid; o < 1280; o += 256) {
        int t = o / 10, cc = o % 10;
        float s = sb3[cc];
        const float* yr = Y_s + t * 84;
#pragma unroll 4
        for (int d = 0; d < 84; d++) s += yr[d] * sw3[d * 10 + cc];
        out[(size_t)(t0 + t) * 10 + cc] = s;
    }
}

// ---------------------------------------------------------------------------
extern "C" void kernel_launch(void* const* d_in, const int* in_sizes, int n_in,
                              void* d_out, int out_size)
{
    const float* x       = (const float*)d_in[0];
    const float* conv1_w = (const float*)d_in[1];
    const float* conv1_b = (const float*)d_in[2];
    const float* conv2_w = (const float*)d_in[3];
    const float* conv2_b = (const float*)d_in[4];
    const float* fc1_w   = (const float*)d_in[5];
    const float* fc1_b   = (const float*)d_in[6];
    const float* fc2_w   = (const float*)d_in[7];
    const float* fc2_b   = (const float*)d_in[8];
    const float* gate_w  = (const float*)d_in[9];
    const float* exp_w1  = (const float*)d_in[10];
    const float* exp_b1  = (const float*)d_in[11];
    const float* exp_w2  = (const float*)d_in[12];
    const float* exp_b2  = (const float*)d_in[13];
    const float* fc3_w   = (const float*)d_in[14];
    const float* fc3_b   = (const float*)d_in[15];
    float* out = (float*)d_out;

    const int B = B_TOTAL;

    float *h1, *h2, *h3, *h4;
    cudaGetSymbolAddress((void**)&h1, g_h1);
    cudaGetSymbolAddress((void**)&h2, g_h2);
    cudaGetSymbolAddress((void**)&h3, g_h3);
    cudaGetSymbolAddress((void**)&h4, g_h4);

    cudaFuncSetAttribute(moe_fc3_kernel,
                         cudaFuncAttributeMaxDynamicSharedMemorySize,
                         MOE_SMEM_FLOATS * (int)sizeof(float));
    cudaFuncSetAttribute(conv1_kernel,
                         cudaFuncAttributeMaxDynamicSharedMemorySize,
                         C1_SMEM_FLOATS * (int)sizeof(float));

    // weight pre-pass (independent of conv path)
    prep_w1<<<(64 * W1CH + 255) / 256, 256>>>(exp_w1);
    prep_w2<<<(64 * W2CH + 255) / 256, 256>>>(exp_w2);

    conv1_kernel<<<B / 2, 256, C1_SMEM_FLOATS * (int)sizeof(float)>>>(
        x, conv1_w, conv1_b, h1);
    conv2_kernel<<<(B + 2) / 3, 256>>>(h1, conv2_w, conv2_b, h2, B);

    dim3 g1(2, B / 64);
    gemm_bias_relu<<<g1, 256>>>(h2, fc1_w, fc1_b, h3, B, 120, 400, 1);
    dim3 g2(2, B / 64);
    gemm_bias_relu<<<g2, 256>>>(h3, fc2_w, fc2_b, h4, B, 84, 120, 1);

    moe_fc3_kernel<<<B / 128, 256, MOE_SMEM_FLOATS * (int)sizeof(float)>>>(
        h4, gate_w, exp_b1, exp_b2, fc3_w, fc3_b, out);
}